// round 8
// baseline (speedup 1.0000x reference)
#include <cuda_runtime.h>
#include <cuda_bf16.h>
#include <cstdint>

// XLSTM social pooling (N=256 agents, B=64, H=128, last timestep only):
// out[i,b,:] = mean over j!=i with ||p_i-p_j||<=r of h_last[j,b,:]
//
// R8 (vs R6 @14.8us, latency-bound: issue 49%, L1 48%):
//  - neighbor lists store u32 PRE-SCALED byte offsets (j*512): uint4 load
//    yields 4 ready offsets, no unpack ALU, address = per-lane base + off
//  - 1-deep prefetch of the next index quad (lists padded +4 entries so the
//    unconditional prefetch stays in bounds)
//  - 4 independent f32x2 accumulator chains (8-cyc/iter chain depth vs 16)

#define NA    256
#define NROWS 257                 // +1 all-zero padding row
#define NB    64
#define SEQL  20
#define HID   128
#define ROWB  (HID * 4)           // 512 bytes per row

#define I_PER_BLOCK 128           // 2 blocks per batch
#define THREADS     1024          // 32 warps -> 4 agents per warp
#define NWARPS      (THREADS / 32)
#define LISTCAP     (NA + 4)      // +4 pad so prefetch never over-reads
#define SMEM_BYTES  (NROWS * HID * 4 + NA * 8 + NWARPS * LISTCAP * 4)

__device__ __forceinline__ void addx2(unsigned long long& acc, unsigned long long v) {
    asm("add.rn.f32x2 %0, %1, %2;" : "=l"(acc) : "l"(acc), "l"(v));
}

__global__ __launch_bounds__(THREADS, 1)
void social_pool_kernel(const float* __restrict__ hidden,
                        const float* __restrict__ pos,
                        const float* __restrict__ radius_ptr,
                        float* __restrict__ out)
{
    extern __shared__ float smem[];
    float*    hs    = smem;                              // [257][128] f32
    float2*   ps    = (float2*)(smem + NROWS * HID);     // [256]
    uint32_t* lists = (uint32_t*)(ps + NA);              // [32][LISTCAP]

    const int b     = blockIdx.x >> 1;
    const int ihalf = blockIdx.x & 1;

    // --- stage positions (last timestep) ---
    for (int j = threadIdx.x; j < NA; j += THREADS) {
        const float* pp = pos + ((size_t)(j * NB + b) * SEQL + (SEQL - 1)) * 2;
        ps[j] = make_float2(pp[0], pp[1]);
    }

    // --- stage h_last tile [256][128] (float4, coalesced 512B rows) ---
    #pragma unroll
    for (int t = threadIdx.x; t < NA * (HID / 4); t += THREADS) {
        const int j = t >> 5;
        const int c = t & 31;
        const float4* src =
            (const float4*)(hidden + ((size_t)(j * NB + b) * SEQL + (SEQL - 1)) * HID) + c;
        ((float4*)hs)[t] = *src;
    }
    // zero padding row 256 (32 float4)
    if (threadIdx.x < HID / 4) {
        ((float4*)(hs + NA * HID))[threadIdx.x] = make_float4(0.f, 0.f, 0.f, 0.f);
    }
    __syncthreads();

    const float r  = *radius_ptr;
    const float r2 = r * r;

    const int warp = threadIdx.x >> 5;
    const int lane = threadIdx.x & 31;
    const unsigned lmask_lt = (1u << lane) - 1u;

    uint32_t*   mylist = lists + warp * LISTCAP;
    const char* hbase  = (const char*)hs + lane * 16;    // per-lane 16B slice

    for (int ii = warp; ii < I_PER_BLOCK; ii += NWARPS) {
        const int i = ihalf * I_PER_BLOCK + ii;
        const float2 pi = ps[i];

        // --- phase 1: build list of row byte-offsets (j*512) ---
        int cnt = 0;
        #pragma unroll
        for (int w = 0; w < 8; w++) {
            const int j = w * 32 + lane;
            const float2 pj = ps[j];
            const float dx = pi.x - pj.x;
            const float dy = pi.y - pj.y;
            const bool ok = (dx * dx + dy * dy <= r2) && (j != i);
            const unsigned m = __ballot_sync(0xffffffffu, ok);
            if (ok) mylist[cnt + __popc(m & lmask_lt)] = (uint32_t)(j << 9);
            cnt += __popc(m);
        }
        // pad to multiple of 4 with dummy offset -> zero row
        const int pad = (-cnt) & 3;
        if (lane < pad) mylist[cnt + lane] = (uint32_t)(NA << 9);
        __syncwarp();

        // --- phase 2: uniform drain, 4 visits/iter, prefetched indices ---
        unsigned long long a0 = 0ull, a1 = 0ull, a2 = 0ull, a3 = 0ull;
        const int n4 = (cnt + 3) >> 2;
        uint4 q = ((const uint4*)mylist)[0];
        for (int n = 0; n < n4; n++) {
            const uint4 qn = ((const uint4*)mylist)[n + 1];   // prefetch (padded)
            const ulonglong2 h0 = *(const ulonglong2*)(hbase + q.x);
            const ulonglong2 h1 = *(const ulonglong2*)(hbase + q.y);
            const ulonglong2 h2 = *(const ulonglong2*)(hbase + q.z);
            const ulonglong2 h3 = *(const ulonglong2*)(hbase + q.w);
            addx2(a0, h0.x); addx2(a1, h0.y);
            addx2(a2, h1.x); addx2(a3, h1.y);
            addx2(a0, h2.x); addx2(a1, h2.y);
            addx2(a2, h3.x); addx2(a3, h3.y);
            q = qn;
        }
        addx2(a0, a2);       // combine the two chains per half
        addx2(a1, a3);

        const float scale = 1.0f / fmaxf((float)cnt, 1.0f);
        const float2 v01 = *(const float2*)&a0;
        const float2 v23 = *(const float2*)&a1;
        float4 o;
        o.x = v01.x * scale; o.y = v01.y * scale;
        o.z = v23.x * scale; o.w = v23.y * scale;
        ((float4*)(out + ((size_t)i * NB + b) * HID))[lane] = o;

        __syncwarp();   // list reuse fence before next agent's build
    }
}

extern "C" void kernel_launch(void* const* d_in, const int* in_sizes, int n_in,
                              void* d_out, int out_size)
{
    const float* hidden = (const float*)d_in[0];   // (256,64,20,128) f32
    const float* pos    = (const float*)d_in[1];   // (256,64,20,2)  f32
    const float* radius = (const float*)d_in[2];   // scalar f32
    float* out = (float*)d_out;                    // (256,64,128)   f32

    cudaFuncSetAttribute(social_pool_kernel,
                         cudaFuncAttributeMaxDynamicSharedMemorySize,
                         SMEM_BYTES);

    social_pool_kernel<<<NB * 2, THREADS, SMEM_BYTES>>>(hidden, pos, radius, out);
}